// round 14
// baseline (speedup 1.0000x reference)
#include <cuda_runtime.h>
#include <cstdint>

// Problem constants (fixed by the dataset: emb [8,8,1024,1024] f32, gt_seg [8,1024,1024] i32)
#define B_      8
#define D_      8
#define HW_     (1024 * 1024)
#define C_      5
#define CTAS_   18            // CTAs per batch -> 144 total blocks (<=148 SMs, 1 wave)
#define THREADS_ 256
#define NWARPS_ (THREADS_ / 32)
#define TOTAL_CTAS_ (CTAS_ * B_)
#define NVALS_  50
#define NPAIRS_ (C_ * (C_ - 1))   // 20 ordered pairs

// ---- TMA-bulk SMEM pipeline geometry ----
#define PXS_        1024                       // pixels per stage (4 per thread)
#define STAGES_PB_  (HW_ / PXS_)               // 1024 stages per batch
#define SEG_BYTES_  (PXS_ * 4)                 // 4 KB
#define ROW_BYTES_  (PXS_ * 4)                 // 4 KB per dim
#define STAGE_BYTES_ (SEG_BYTES_ + D_ * ROW_BYTES_)  // 36 KB
#define NS_         4                          // ring depth
#define MBAR_OFF_   0                          // NS_ pairs of (full, empty) mbarriers
#define DATA_OFF_   1024
#define SMEM_DYN_   (DATA_OFF_ + NS_ * STAGE_BYTES_)  // 148480 B

// NVALS layout per (batch, block):
//   [0..31]  S[c][d] c<4 | [32..39] T[d] | [40..43] q_c c<4 | [44] qT | [45..48] cnt_c c<4 | [49] n

typedef unsigned long long u64;

__device__ float g_partials[B_][CTAS_][NVALS_];
__device__ unsigned int g_done;   // zero at load; last block resets to 0 each launch

// ---- packed f32x2 helpers ----
__device__ __forceinline__ u64 pk2(float lo, float hi) {
    u64 r; asm("mov.b64 %0, {%1, %2};" : "=l"(r) : "f"(lo), "f"(hi)); return r;
}
__device__ __forceinline__ float2 upk2(u64 v) {
    float2 f; asm("mov.b64 {%0, %1}, %2;" : "=f"(f.x), "=f"(f.y) : "l"(v)); return f;
}
__device__ __forceinline__ void fma2(u64& a, u64 m, u64 v) {
    asm("fma.rn.f32x2 %0, %1, %2, %0;" : "+l"(a) : "l"(m), "l"(v));
}
__device__ __forceinline__ void add2(u64& a, u64 v) {
    asm("add.rn.f32x2 %0, %0, %1;" : "+l"(a) : "l"(v));
}

// ---- smem / mbarrier / bulk-copy helpers ----
__device__ __forceinline__ uint32_t smem_u32(const void* p) {
    uint32_t a; asm("{ .reg .u64 t; cvta.to.shared.u64 t, %1; cvt.u32.u64 %0, t; }" : "=r"(a) : "l"(p));
    return a;
}
__device__ __forceinline__ void mbar_init(uint32_t a, uint32_t cnt) {
    asm volatile("mbarrier.init.shared.b64 [%0], %1;" :: "r"(a), "r"(cnt) : "memory");
}
__device__ __forceinline__ void mbar_expect_tx(uint32_t a, uint32_t bytes) {
    asm volatile("mbarrier.arrive.expect_tx.shared.b64 _, [%0], %1;" :: "r"(a), "r"(bytes) : "memory");
}
__device__ __forceinline__ void mbar_arrive(uint32_t a) {
    asm volatile("mbarrier.arrive.shared.b64 _, [%0];" :: "r"(a) : "memory");
}
__device__ __forceinline__ void mbar_wait_acq(uint32_t a, uint32_t ph) {
    asm volatile(
        "{\n\t.reg .pred P;\n\t"
        "WL_%=:\n\t"
        "mbarrier.try_wait.parity.acquire.cta.shared::cta.b64 P, [%0], %1, 0x989680;\n\t"
        "@P bra.uni WD_%=;\n\t"
        "bra.uni WL_%=;\n\t"
        "WD_%=:\n\t}"
        :: "r"(a), "r"(ph) : "memory");
}
__device__ __forceinline__ void mbar_wait_rlx(uint32_t a, uint32_t ph) {
    asm volatile(
        "{\n\t.reg .pred P;\n\t"
        "WL_%=:\n\t"
        "mbarrier.try_wait.parity.relaxed.cta.shared::cta.b64 P, [%0], %1, 0x989680;\n\t"
        "@P bra.uni WD_%=;\n\t"
        "bra.uni WL_%=;\n\t"
        "WD_%=:\n\t}"
        :: "r"(a), "r"(ph) : "memory");
}
// Bulk copy with L2 evict_first policy — streaming data, zero reuse.
__device__ __forceinline__ void bulk_g2s_ef(uint32_t dst, const void* src, uint32_t bytes,
                                            uint32_t mbar, u64 pol) {
    asm volatile("cp.async.bulk.shared::cta.global.mbarrier::complete_tx::bytes.L2::cache_hint"
                 " [%0], [%1], %2, [%3], %4;"
                 :: "r"(dst), "l"(src), "r"(bytes), "r"(mbar), "l"(pol) : "memory");
}
__device__ __forceinline__ u64 mk_policy_ef() {
    u64 p; asm("createpolicy.fractional.L2::evict_first.b64 %0, 1.0;" : "=l"(p));
    return p;
}

__device__ __forceinline__ void issue_stage(uint32_t sb, int slot, int st,
                                            const char* seg_g, const char* emb_g, u64 pol) {
    const uint32_t full = sb + MBAR_OFF_ + slot * 16;
    const uint32_t dst  = sb + DATA_OFF_ + slot * STAGE_BYTES_;
    const size_t px0 = (size_t)st * PXS_;
    mbar_expect_tx(full, STAGE_BYTES_);
    bulk_g2s_ef(dst, seg_g + px0 * 4, SEG_BYTES_, full, pol);
#pragma unroll
    for (int d = 0; d < D_; d++)
        bulk_g2s_ef(dst + SEG_BYTES_ + d * ROW_BYTES_,
                    emb_g + ((size_t)d * HW_ + px0) * 4, ROW_BYTES_, full, pol);
}

__global__ void __launch_bounds__(THREADS_, 1)
lane_loss_fused_kernel(const float* __restrict__ emb, const int* __restrict__ seg,
                       float* __restrict__ out) {
    extern __shared__ char smem[];
    const uint32_t sb = smem_u32(smem);
    const int b  = blockIdx.y;
    const int cj = blockIdx.x;
    const int tid = threadIdx.x;
    const int lane = tid & 31;

    const char* seg_g = (const char*)(seg + (size_t)b * HW_);
    const char* emb_g = (const char*)(emb + (size_t)b * D_ * HW_);
    const u64 pol = mk_policy_ef();

    // barriers: full(slot) at +slot*16, empty(slot) at +slot*16+8
    if (tid == 0) {
#pragma unroll
        for (int s = 0; s < NS_; s++) {
            mbar_init(sb + MBAR_OFF_ + s * 16, 1);        // full: 1 expect_tx arrive + tx bytes
            mbar_init(sb + MBAR_OFF_ + s * 16 + 8, NWARPS_); // empty: one elected arrive per warp
        }
    }
    __syncthreads();

    // Stages assigned to this CTA: st = cj + k*CTAS_, k = 0..nmine-1
    const int nmine = (STAGES_PB_ - cj + CTAS_ - 1) / CTAS_;   // 57 or 56 (>= NS_)

    // Producer prologue: fill the ring
    if (tid == 0) {
#pragma unroll
        for (int k = 0; k < NS_; k++)
            issue_stage(sb, k, cj + k * CTAS_, seg_g, emb_g, pol);
    }

    // ---------------- Pass 1: pipelined streaming reduction ----------------
    u64 accS[4][D_], accT[D_], accQ[4], accQT, accC[4];
#pragma unroll
    for (int c = 0; c < 4; c++) { accQ[c] = 0ull; accC[c] = 0ull;
#pragma unroll
        for (int d = 0; d < D_; d++) accS[c][d] = 0ull; }
#pragma unroll
    for (int d = 0; d < D_; d++) accT[d] = 0ull;
    accQT = 0ull;

    int slot = 0, ph = 0;            // shared cursor: refill slot == consume slot

    for (int k = 0; k < nmine; k++) {
        const uint32_t full  = sb + MBAR_OFF_ + slot * 16;
        const uint32_t empty = full + 8;
        mbar_wait_acq(full, ph);

        // (a) Drain the stage into registers first (144 B/thread)
        const char* base = smem + DATA_OFF_ + slot * STAGE_BYTES_;
        const int4 s4 = *(const int4*)(base + tid * 16);
        float4 v[D_];
#pragma unroll
        for (int d = 0; d < D_; d++)
            v[d] = *(const float4*)(base + SEG_BYTES_ + d * ROW_BYTES_ + tid * 16);

        // (b) Release the slot immediately — one elected arrive per warp
        __syncwarp();
        if (lane == 0) mbar_arrive(empty);

        // (c) Refill this slot with stage k+NS right away (gated on loads, not compute)
        if (tid == 0 && k + NS_ < nmine) {
            mbar_wait_rlx(empty, ph);          // empty phase cadence == full phase cadence
            issue_stage(sb, slot, cj + (k + NS_) * CTAS_, seg_g, emb_g, pol);
        }

        // (d) Compute from registers
        u64 m01[4], m23[4];
#pragma unroll
        for (int c = 0; c < 4; c++) {
            m01[c] = pk2(s4.x == c ? 1.f : 0.f, s4.y == c ? 1.f : 0.f);
            m23[c] = pk2(s4.z == c ? 1.f : 0.f, s4.w == c ? 1.f : 0.f);
        }

        u64 q01 = 0ull, q23 = 0ull;
#pragma unroll
        for (int d = 0; d < D_; d++) {
            const u64 v01 = pk2(v[d].x, v[d].y);
            const u64 v23 = pk2(v[d].z, v[d].w);
            fma2(q01, v01, v01);
            fma2(q23, v23, v23);
            add2(accT[d], v01);
            add2(accT[d], v23);
#pragma unroll
            for (int c = 0; c < 4; c++) {
                fma2(accS[c][d], m01[c], v01);
                fma2(accS[c][d], m23[c], v23);
            }
        }
#pragma unroll
        for (int c = 0; c < 4; c++) {
            fma2(accQ[c], m01[c], q01);
            fma2(accQ[c], m23[c], q23);
            add2(accC[c], m01[c]);
            add2(accC[c], m23[c]);
        }
        add2(accQT, q01);
        add2(accQT, q23);

        if (++slot == NS_) { slot = 0; ph ^= 1; }
    }

    // Collapse packed lanes -> 50 per-thread scalars
    float vals[NVALS_];
#pragma unroll
    for (int c = 0; c < 4; c++)
#pragma unroll
        for (int d = 0; d < D_; d++) { float2 f = upk2(accS[c][d]); vals[c * D_ + d] = f.x + f.y; }
#pragma unroll
    for (int d = 0; d < D_; d++) { float2 f = upk2(accT[d]); vals[32 + d] = f.x + f.y; }
#pragma unroll
    for (int c = 0; c < 4; c++) { float2 f = upk2(accQ[c]); vals[40 + c] = f.x + f.y; }
    { float2 f = upk2(accQT); vals[44] = f.x + f.y; }
#pragma unroll
    for (int c = 0; c < 4; c++) { float2 f = upk2(accC[c]); vals[45 + c] = f.x + f.y; }
    vals[49] = (float)(nmine * 4);   // pixels per thread this block

    // Intra-warp butterfly reduce
#pragma unroll
    for (int kk = 0; kk < NVALS_; kk++)
#pragma unroll
        for (int off = 16; off > 0; off >>= 1)
            vals[kk] += __shfl_xor_sync(0xffffffffu, vals[kk], off);

    __shared__ float red[NWARPS_][NVALS_];
    const int warp = tid >> 5;
    if (lane == 0)
#pragma unroll
        for (int kk = 0; kk < NVALS_; kk++) red[warp][kk] = vals[kk];
    __syncthreads();
    if (tid < NVALS_) {
        float s = 0.f;
#pragma unroll
        for (int w = 0; w < NWARPS_; w++) s += red[w][tid];
        g_partials[b][cj][tid] = s;
    }

    // ---------------- Last-block-done handoff ----------------
    __shared__ unsigned int amLast;
    __threadfence();
    if (tid == 0) {
        unsigned int v = atomicAdd(&g_done, 1u);
        amLast = (v == TOTAL_CTAS_ - 1) ? 1u : 0u;
    }
    __syncthreads();
    if (!amLast) return;
    __threadfence();
    if (tid == 0) g_done = 0;

    // ---------------- Pass 2: finalize (fp32, deterministic) ----------------
    __shared__ float sv[B_][NVALS_];
    __shared__ float mean_s[B_][C_][D_];
    __shared__ float sum_s[B_][C_][D_];
    __shared__ float var_s[B_][C_];
    __shared__ float hinge_s[B_][NPAIRS_];
    const int t = tid;

    for (int idx = t; idx < B_ * NVALS_; idx += THREADS_) {
        const int bb = idx / NVALS_, kk = idx % NVALS_;
        float s = 0.f;
#pragma unroll
        for (int j = 0; j < CTAS_; j++) s += g_partials[bb][j][kk];
        sv[bb][kk] = s;
    }
    __syncthreads();

    for (int idx = t; idx < B_ * C_ * D_; idx += THREADS_) {
        const int bb = idx / (C_ * D_);
        const int c  = (idx / D_) % C_;
        const int d  = idx % D_;
        float sm, cn;
        if (c < 4) { sm = sv[bb][c * D_ + d]; cn = sv[bb][45 + c]; }
        else {
            sm = sv[bb][32 + d] - (sv[bb][0 * D_ + d] + sv[bb][1 * D_ + d] +
                                   sv[bb][2 * D_ + d] + sv[bb][3 * D_ + d]);
            cn = sv[bb][49] - (sv[bb][45] + sv[bb][46] + sv[bb][47] + sv[bb][48]);
        }
        sum_s[bb][c][d]  = sm;
        mean_s[bb][c][d] = sm / cn;
    }
    __syncthreads();

    for (int idx = t; idx < B_ * C_; idx += THREADS_) {
        const int bb = idx / C_, c = idx % C_;
        float q;
        if (c < 4) q = sv[bb][40 + c];
        else       q = sv[bb][44] - (sv[bb][40] + sv[bb][41] + sv[bb][42] + sv[bb][43]);
        float m2 = 0.f;
#pragma unroll
        for (int d = 0; d < D_; d++) m2 += sum_s[bb][c][d] * mean_s[bb][c][d];
        float ssv = q - m2;
        if (ssv < 0.f) ssv = 0.f;
        const float r = sqrtf(ssv) - 0.5f;           // SIGMA_V
        var_s[bb][c] = r > 0.f ? r : 0.f;
    }

    for (int idx = t; idx < B_ * NPAIRS_; idx += THREADS_) {
        const int bb = idx / NPAIRS_, p = idx % NPAIRS_;
        const int i = p / (C_ - 1);
        int j = p % (C_ - 1);
        if (j >= i) j++;
        float d2 = 0.f;
#pragma unroll
        for (int d = 0; d < D_; d++) {
            const float df = mean_s[bb][i][d] - mean_s[bb][j][d];
            d2 += df * df;
        }
        const float h = 3.0f - sqrtf(d2);            // SIGMA_D
        hinge_s[bb][p] = h > 0.f ? h : 0.f;
    }
    __syncthreads();

    if (t == 0) {
        float total = 0.f;
        for (int bb = 0; bb < B_; bb++) {
            float v = 0.f;
#pragma unroll
            for (int c = 0; c < C_; c++) v += var_s[bb][c];
            float dl = 0.f;
#pragma unroll
            for (int p = 0; p < NPAIRS_; p++) dl += hinge_s[bb][p];
            total += v / (float)C_ + dl / (float)NPAIRS_;
        }
        out[0] = total / (float)B_;
    }
}

extern "C" void kernel_launch(void* const* d_in, const int* in_sizes, int n_in,
                              void* d_out, int out_size) {
    const float* emb = (const float*)d_in[0];   // [8, 8, 1024, 1024] f32
    const int*   seg = (const int*)d_in[1];     // [8, 1024, 1024] i32
    (void)in_sizes; (void)n_in; (void)out_size;

    cudaFuncSetAttribute(lane_loss_fused_kernel,
                         cudaFuncAttributeMaxDynamicSharedMemorySize, SMEM_DYN_);
    dim3 grid(CTAS_, B_);
    lane_loss_fused_kernel<<<grid, THREADS_, SMEM_DYN_>>>(emb, seg, (float*)d_out);
}

// round 15
// speedup vs baseline: 1.5139x; 1.5139x over previous
#include <cuda_runtime.h>
#include <cstdint>

// Problem constants (fixed by the dataset: emb [8,8,1024,1024] f32, gt_seg [8,1024,1024] i32)
#define B_      8
#define D_      8
#define HW_     (1024 * 1024)
#define C_      5
#define CTAS_   18            // CTAs per batch -> 144 total blocks (<=148 SMs, 1 wave)
#define THREADS_ 256
#define NWARPS_ (THREADS_ / 32)
#define TOTAL_CTAS_ (CTAS_ * B_)
#define NVALS_  50
#define NPAIRS_ (C_ * (C_ - 1))   // 20 ordered pairs

// ---- TMA-bulk SMEM pipeline geometry ----
#define PXS_        1024                       // pixels per stage (4 per thread)
#define STAGES_PB_  (HW_ / PXS_)               // 1024 stages per batch
#define SEG_BYTES_  (PXS_ * 4)                 // 4 KB
#define ROW_BYTES_  (PXS_ * 4)                 // 4 KB per dim
#define STAGE_BYTES_ (SEG_BYTES_ + D_ * ROW_BYTES_)  // 36 KB
#define NS_         5                          // ring depth (185 KB < 227 KB opt-in cap)
#define MBAR_OFF_   0                          // NS_ pairs of (full, empty) mbarriers
#define DATA_OFF_   1024
#define SMEM_DYN_   (DATA_OFF_ + NS_ * STAGE_BYTES_)  // 185344 B

// NVALS layout per (batch, block):
//   [0..31]  S[c][d] c<4 | [32..39] T[d] | [40..43] q_c c<4 | [44] qT | [45..48] cnt_c c<4 | [49] n

typedef unsigned long long u64;

__device__ float g_partials[B_][CTAS_][NVALS_];
__device__ unsigned int g_done;   // zero at load; last block resets to 0 each launch

// ---- packed f32x2 helpers ----
__device__ __forceinline__ u64 pk2(float lo, float hi) {
    u64 r; asm("mov.b64 %0, {%1, %2};" : "=l"(r) : "f"(lo), "f"(hi)); return r;
}
__device__ __forceinline__ float2 upk2(u64 v) {
    float2 f; asm("mov.b64 {%0, %1}, %2;" : "=f"(f.x), "=f"(f.y) : "l"(v)); return f;
}
__device__ __forceinline__ void fma2(u64& a, u64 m, u64 v) {
    asm("fma.rn.f32x2 %0, %1, %2, %0;" : "+l"(a) : "l"(m), "l"(v));
}
__device__ __forceinline__ void add2(u64& a, u64 v) {
    asm("add.rn.f32x2 %0, %0, %1;" : "+l"(a) : "l"(v));
}

// ---- smem / mbarrier / bulk-copy helpers ----
__device__ __forceinline__ uint32_t smem_u32(const void* p) {
    uint32_t a; asm("{ .reg .u64 t; cvta.to.shared.u64 t, %1; cvt.u32.u64 %0, t; }" : "=r"(a) : "l"(p));
    return a;
}
__device__ __forceinline__ void mbar_init(uint32_t a, uint32_t cnt) {
    asm volatile("mbarrier.init.shared.b64 [%0], %1;" :: "r"(a), "r"(cnt) : "memory");
}
__device__ __forceinline__ void mbar_expect_tx(uint32_t a, uint32_t bytes) {
    asm volatile("mbarrier.arrive.expect_tx.shared.b64 _, [%0], %1;" :: "r"(a), "r"(bytes) : "memory");
}
__device__ __forceinline__ void mbar_arrive(uint32_t a) {
    asm volatile("mbarrier.arrive.shared.b64 _, [%0];" :: "r"(a) : "memory");
}
__device__ __forceinline__ void mbar_wait_acq(uint32_t a, uint32_t ph) {
    asm volatile(
        "{\n\t.reg .pred P;\n\t"
        "WL_%=:\n\t"
        "mbarrier.try_wait.parity.acquire.cta.shared::cta.b64 P, [%0], %1, 0x989680;\n\t"
        "@P bra.uni WD_%=;\n\t"
        "bra.uni WL_%=;\n\t"
        "WD_%=:\n\t}"
        :: "r"(a), "r"(ph) : "memory");
}
__device__ __forceinline__ void mbar_wait_rlx(uint32_t a, uint32_t ph) {
    asm volatile(
        "{\n\t.reg .pred P;\n\t"
        "WL_%=:\n\t"
        "mbarrier.try_wait.parity.relaxed.cta.shared::cta.b64 P, [%0], %1, 0x989680;\n\t"
        "@P bra.uni WD_%=;\n\t"
        "bra.uni WL_%=;\n\t"
        "WD_%=:\n\t}"
        :: "r"(a), "r"(ph) : "memory");
}
// Default L2 policy — R14 showed evict_first badly hurts saturated streaming reads.
__device__ __forceinline__ void bulk_g2s(uint32_t dst, const void* src, uint32_t bytes, uint32_t mbar) {
    asm volatile("cp.async.bulk.shared::cta.global.mbarrier::complete_tx::bytes [%0], [%1], %2, [%3];"
                 :: "r"(dst), "l"(src), "r"(bytes), "r"(mbar) : "memory");
}

__device__ __forceinline__ void issue_stage(uint32_t sb, int slot, int st,
                                            const char* seg_g, const char* emb_g) {
    const uint32_t full = sb + MBAR_OFF_ + slot * 16;
    const uint32_t dst  = sb + DATA_OFF_ + slot * STAGE_BYTES_;
    const size_t px0 = (size_t)st * PXS_;
    mbar_expect_tx(full, STAGE_BYTES_);
    bulk_g2s(dst, seg_g + px0 * 4, SEG_BYTES_, full);
#pragma unroll
    for (int d = 0; d < D_; d++)
        bulk_g2s(dst + SEG_BYTES_ + d * ROW_BYTES_,
                 emb_g + ((size_t)d * HW_ + px0) * 4, ROW_BYTES_, full);
}

__global__ void __launch_bounds__(THREADS_, 1)
lane_loss_fused_kernel(const float* __restrict__ emb, const int* __restrict__ seg,
                       float* __restrict__ out) {
    extern __shared__ char smem[];
    const uint32_t sb = smem_u32(smem);
    const int b  = blockIdx.y;
    const int cj = blockIdx.x;
    const int tid = threadIdx.x;
    const int lane = tid & 31;

    const char* seg_g = (const char*)(seg + (size_t)b * HW_);
    const char* emb_g = (const char*)(emb + (size_t)b * D_ * HW_);

    // barriers: full(slot) at +slot*16, empty(slot) at +slot*16+8
    if (tid == 0) {
#pragma unroll
        for (int s = 0; s < NS_; s++) {
            mbar_init(sb + MBAR_OFF_ + s * 16, 1);        // full: 1 expect_tx arrive + tx bytes
            mbar_init(sb + MBAR_OFF_ + s * 16 + 8, NWARPS_); // empty: one elected arrive per warp
        }
    }
    __syncthreads();

    // Stages assigned to this CTA: st = cj + k*CTAS_, k = 0..nmine-1
    const int nmine = (STAGES_PB_ - cj + CTAS_ - 1) / CTAS_;   // 57 or 56 (>= NS_)

    // Producer prologue: fill the ring
    if (tid == 0) {
#pragma unroll
        for (int k = 0; k < NS_; k++)
            issue_stage(sb, k, cj + k * CTAS_, seg_g, emb_g);
    }

    // ---------------- Pass 1: pipelined streaming reduction ----------------
    u64 accS[4][D_], accT[D_], accQ[4], accQT, accC[4];
#pragma unroll
    for (int c = 0; c < 4; c++) { accQ[c] = 0ull; accC[c] = 0ull;
#pragma unroll
        for (int d = 0; d < D_; d++) accS[c][d] = 0ull; }
#pragma unroll
    for (int d = 0; d < D_; d++) accT[d] = 0ull;
    accQT = 0ull;

    int slot = 0, ph = 0;            // shared cursor: refill slot == consume slot

    for (int k = 0; k < nmine; k++) {
        const uint32_t full  = sb + MBAR_OFF_ + slot * 16;
        const uint32_t empty = full + 8;
        mbar_wait_acq(full, ph);

        // (a) Drain the stage into registers first (144 B/thread)
        const char* base = smem + DATA_OFF_ + slot * STAGE_BYTES_;
        const int4 s4 = *(const int4*)(base + tid * 16);
        float4 v[D_];
#pragma unroll
        for (int d = 0; d < D_; d++)
            v[d] = *(const float4*)(base + SEG_BYTES_ + d * ROW_BYTES_ + tid * 16);

        // (b) Release the slot immediately — one elected arrive per warp
        __syncwarp();
        if (lane == 0) mbar_arrive(empty);

        // (c) Refill this slot with stage k+NS right away (gated on loads, not compute)
        if (tid == 0 && k + NS_ < nmine) {
            mbar_wait_rlx(empty, ph);          // empty phase cadence == full phase cadence
            issue_stage(sb, slot, cj + (k + NS_) * CTAS_, seg_g, emb_g);
        }

        // (d) Compute from registers
        u64 m01[4], m23[4];
#pragma unroll
        for (int c = 0; c < 4; c++) {
            m01[c] = pk2(s4.x == c ? 1.f : 0.f, s4.y == c ? 1.f : 0.f);
            m23[c] = pk2(s4.z == c ? 1.f : 0.f, s4.w == c ? 1.f : 0.f);
        }

        u64 q01 = 0ull, q23 = 0ull;
#pragma unroll
        for (int d = 0; d < D_; d++) {
            const u64 v01 = pk2(v[d].x, v[d].y);
            const u64 v23 = pk2(v[d].z, v[d].w);
            fma2(q01, v01, v01);
            fma2(q23, v23, v23);
            add2(accT[d], v01);
            add2(accT[d], v23);
#pragma unroll
            for (int c = 0; c < 4; c++) {
                fma2(accS[c][d], m01[c], v01);
                fma2(accS[c][d], m23[c], v23);
            }
        }
#pragma unroll
        for (int c = 0; c < 4; c++) {
            fma2(accQ[c], m01[c], q01);
            fma2(accQ[c], m23[c], q23);
            add2(accC[c], m01[c]);
            add2(accC[c], m23[c]);
        }
        add2(accQT, q01);
        add2(accQT, q23);

        if (++slot == NS_) { slot = 0; ph ^= 1; }
    }

    // Collapse packed lanes -> 50 per-thread scalars
    float vals[NVALS_];
#pragma unroll
    for (int c = 0; c < 4; c++)
#pragma unroll
        for (int d = 0; d < D_; d++) { float2 f = upk2(accS[c][d]); vals[c * D_ + d] = f.x + f.y; }
#pragma unroll
    for (int d = 0; d < D_; d++) { float2 f = upk2(accT[d]); vals[32 + d] = f.x + f.y; }
#pragma unroll
    for (int c = 0; c < 4; c++) { float2 f = upk2(accQ[c]); vals[40 + c] = f.x + f.y; }
    { float2 f = upk2(accQT); vals[44] = f.x + f.y; }
#pragma unroll
    for (int c = 0; c < 4; c++) { float2 f = upk2(accC[c]); vals[45 + c] = f.x + f.y; }
    vals[49] = (float)(nmine * 4);   // pixels per thread this block

    // Intra-warp butterfly reduce
#pragma unroll
    for (int kk = 0; kk < NVALS_; kk++)
#pragma unroll
        for (int off = 16; off > 0; off >>= 1)
            vals[kk] += __shfl_xor_sync(0xffffffffu, vals[kk], off);

    __shared__ float red[NWARPS_][NVALS_];
    const int warp = tid >> 5;
    if (lane == 0)
#pragma unroll
        for (int kk = 0; kk < NVALS_; kk++) red[warp][kk] = vals[kk];
    __syncthreads();
    if (tid < NVALS_) {
        float s = 0.f;
#pragma unroll
        for (int w = 0; w < NWARPS_; w++) s += red[w][tid];
        g_partials[b][cj][tid] = s;
    }

    // ---------------- Last-block-done handoff ----------------
    __shared__ unsigned int amLast;
    __threadfence();
    if (tid == 0) {
        unsigned int v = atomicAdd(&g_done, 1u);
        amLast = (v == TOTAL_CTAS_ - 1) ? 1u : 0u;
    }
    __syncthreads();
    if (!amLast) return;
    __threadfence();
    if (tid == 0) g_done = 0;

    // ---------------- Pass 2: finalize (fp32, deterministic) ----------------
    __shared__ float sv[B_][NVALS_];
    __shared__ float mean_s[B_][C_][D_];
    __shared__ float sum_s[B_][C_][D_];
    __shared__ float var_s[B_][C_];
    __shared__ float hinge_s[B_][NPAIRS_];
    const int t = tid;

    for (int idx = t; idx < B_ * NVALS_; idx += THREADS_) {
        const int bb = idx / NVALS_, kk = idx % NVALS_;
        float s = 0.f;
#pragma unroll
        for (int j = 0; j < CTAS_; j++) s += g_partials[bb][j][kk];
        sv[bb][kk] = s;
    }
    __syncthreads();

    for (int idx = t; idx < B_ * C_ * D_; idx += THREADS_) {
        const int bb = idx / (C_ * D_);
        const int c  = (idx / D_) % C_;
        const int d  = idx % D_;
        float sm, cn;
        if (c < 4) { sm = sv[bb][c * D_ + d]; cn = sv[bb][45 + c]; }
        else {
            sm = sv[bb][32 + d] - (sv[bb][0 * D_ + d] + sv[bb][1 * D_ + d] +
                                   sv[bb][2 * D_ + d] + sv[bb][3 * D_ + d]);
            cn = sv[bb][49] - (sv[bb][45] + sv[bb][46] + sv[bb][47] + sv[bb][48]);
        }
        sum_s[bb][c][d]  = sm;
        mean_s[bb][c][d] = sm / cn;
    }
    __syncthreads();

    for (int idx = t; idx < B_ * C_; idx += THREADS_) {
        const int bb = idx / C_, c = idx % C_;
        float q;
        if (c < 4) q = sv[bb][40 + c];
        else       q = sv[bb][44] - (sv[bb][40] + sv[bb][41] + sv[bb][42] + sv[bb][43]);
        float m2 = 0.f;
#pragma unroll
        for (int d = 0; d < D_; d++) m2 += sum_s[bb][c][d] * mean_s[bb][c][d];
        float ssv = q - m2;
        if (ssv < 0.f) ssv = 0.f;
        const float r = sqrtf(ssv) - 0.5f;           // SIGMA_V
        var_s[bb][c] = r > 0.f ? r : 0.f;
    }

    for (int idx = t; idx < B_ * NPAIRS_; idx += THREADS_) {
        const int bb = idx / NPAIRS_, p = idx % NPAIRS_;
        const int i = p / (C_ - 1);
        int j = p % (C_ - 1);
        if (j >= i) j++;
        float d2 = 0.f;
#pragma unroll
        for (int d = 0; d < D_; d++) {
            const float df = mean_s[bb][i][d] - mean_s[bb][j][d];
            d2 += df * df;
        }
        const float h = 3.0f - sqrtf(d2);            // SIGMA_D
        hinge_s[bb][p] = h > 0.f ? h : 0.f;
    }
    __syncthreads();

    if (t == 0) {
        float total = 0.f;
        for (int bb = 0; bb < B_; bb++) {
            float v = 0.f;
#pragma unroll
            for (int c = 0; c < C_; c++) v += var_s[bb][c];
            float dl = 0.f;
#pragma unroll
            for (int p = 0; p < NPAIRS_; p++) dl += hinge_s[bb][p];
            total += v / (float)C_ + dl / (float)NPAIRS_;
        }
        out[0] = total / (float)B_;
    }
}

extern "C" void kernel_launch(void* const* d_in, const int* in_sizes, int n_in,
                              void* d_out, int out_size) {
    const float* emb = (const float*)d_in[0];   // [8, 8, 1024, 1024] f32
    const int*   seg = (const int*)d_in[1];     // [8, 1024, 1024] i32
    (void)in_sizes; (void)n_in; (void)out_size;

    cudaFuncSetAttribute(lane_loss_fused_kernel,
                         cudaFuncAttributeMaxDynamicSharedMemorySize, SMEM_DYN_);
    dim3 grid(CTAS_, B_);
    lane_loss_fused_kernel<<<grid, THREADS_, SMEM_DYN_>>>(emb, seg, (float*)d_out);
}